// round 9
// baseline (speedup 1.0000x reference)
#include <cuda_runtime.h>
#include <math_constants.h>
#include <stdint.h>

#define NTOT     18432
#define TPB      256
#define TILE     256
#define NSTRIP   24
#define NDIAG    24
#define NUNITS   576                 /* 24 diag + 276*2 offdiag halves */
#define GRID     579
#define NWARPS   8
#define V4PT     18                  /* NTOT/4/TPB */
#define GMAX     1024
#define SELMAX   48
#define SMEM_BYTES 4096

static const double NPAIRS_D = 18871296.0;
static const double RAND_STD = 1.75;
static const double IQR_RAND = 2.45;

__device__ double   g_pair_partial[NUNITS];
__device__ double   g_sum_d, g_sumsq_d;
__device__ float    g_qv[4];
__device__ unsigned g_c1[32 * 64];
__device__ unsigned g_c2 = 0;

typedef unsigned long long u64;
__device__ __forceinline__ float sqrt_approx(float x) {
    float r; asm("sqrt.approx.f32 %0, %1;" : "=f"(r) : "f"(x)); return r;
}
__device__ __forceinline__ u64 addx2(u64 a, u64 b) {
    u64 r; asm("add.rn.f32x2 %0, %1, %2;" : "=l"(r) : "l"(a), "l"(b)); return r;
}
__device__ __forceinline__ u64 fmax2(u64 a, u64 b, u64 c) {
    u64 r; asm("fma.rn.f32x2 %0, %1, %2, %3;" : "=l"(r) : "l"(a), "l"(b), "l"(c)); return r;
}
__device__ __forceinline__ u64 pack2(float lo, float hi) {
    u64 r; asm("mov.b64 %0, {%1, %2};" : "=l"(r) : "f"(lo), "f"(hi)); return r;
}
__device__ __forceinline__ void unpack2(u64 v, float& lo, float& hi) {
    asm("mov.b64 {%0, %1}, %2;" : "=f"(lo), "=f"(hi) : "l"(v));
}
__device__ __forceinline__ u64 lds64(unsigned addr) {
    u64 r; asm("ld.shared.b64 %0, [%1];" : "=l"(r) : "r"(addr)); return r;
}
__device__ __forceinline__ unsigned smem_u32(const void* p) {
    unsigned a;
    asm("{ .reg .u64 t; cvta.to.shared.u64 t, %1; cvt.u32.u64 %0, t; }"
        : "=r"(a) : "l"(p));
    return a;
}
__device__ __forceinline__ unsigned fkey(float f) {
    unsigned u = __float_as_uint(f);
    return (u & 0x80000000u) ? ~u : (u | 0x80000000u);
}
__device__ __forceinline__ float funkey(unsigned u) {
    unsigned bits = (u & 0x80000000u) ? (u & 0x7fffffffu) : ~u;
    return __uint_as_float(bits);
}
/* rare-hit handler: pen += relu(0.8 - sqrt(sq)) for one pair */
__device__ __forceinline__ void hit(float s, float& acc) {
    if (s < 0.64f) acc += 0.8f - sqrt_approx(fmaxf(s, 0.0f));
}

__global__ void __launch_bounds__(TPB, 4)
dp_fused_kernel(const float* __restrict__ g, float* __restrict__ out) {
    extern __shared__ unsigned char smem_raw[];
    const int bid = blockIdx.x;
    const int t   = threadIdx.x;
    const int w   = t >> 5;
    const int ln  = t & 31;

    __shared__ unsigned s_wcnt[NWARPS];
    __shared__ unsigned s_tot, s_gcnt;
    __shared__ float    s_fred[NWARPS];
    __shared__ float    s_q[2];
    __shared__ int      s_last;

    if (bid >= 3) {
        /* ========== pairwise: rare-hit branch, packed screen =========== */
        const int pid = bid - 3;
        int a, b, h;
        if (pid < NDIAG) { a = b = pid; h = -1; }
        else {
            int o = pid - NDIAG;
            int tt = o >> 1; h = o & 1;
            a = 0; int rem = tt;
            while (rem >= NSTRIP - 1 - a) { rem -= NSTRIP - 1 - a; ++a; }
            b = a + 1 + rem;
        }

        float acc = 0.f;

        if (h < 0) {
            /* diag: float4 tile, scalar pairs with rare-hit branch */
            float4* tj = (float4*)smem_raw;
            {
                const int j = b * TILE + t;
                float xj = g[3 * j + 0], yj = g[3 * j + 1], zj = g[3 * j + 2];
                tj[t] = make_float4(xj, yj, zj,
                                    fmaf(zj, zj, fmaf(yj, yj, xj * xj)));
            }
            __syncthreads();
            float4 me = tj[t];
            const float R = me.w;
            const float A = -2.0f * me.x, B = -2.0f * me.y, C = -2.0f * me.z;
            #pragma unroll 4
            for (int d = 1; d <= 127; ++d) {
                float4 o = tj[(t + d) & (TILE - 1)];
                float s = fmaf(C, o.z, fmaf(B, o.y, fmaf(A, o.x, R + o.w)));
                hit(s, acc);
            }
            if (t < TILE / 2) {
                float4 o = tj[(t + 128) & (TILE - 1)];
                float s = fmaf(C, o.z, fmaf(B, o.y, fmaf(A, o.x, R + o.w)));
                hit(s, acc);
            }
        } else {
            /* off-diag half: packed SoA pair layout
               layout (u64 units): for m in [0,128): X[m]=(x_{2m},x_{2m+1}),
               Y[m], Z[m], RR[m]; arrays contiguous: X | Y | Z | RR        */
            float* sf = (float*)smem_raw;
            {
                const int j = b * TILE + t;
                float xj = g[3 * j + 0], yj = g[3 * j + 1], zj = g[3 * j + 2];
                const int mi = t >> 1, pi = t & 1;
                sf[          2 * mi + pi] = xj;
                sf[1 * TILE + 2 * mi + pi] = yj;
                sf[2 * TILE + 2 * mi + pi] = zj;
                sf[3 * TILE + 2 * mi + pi] =
                    fmaf(zj, zj, fmaf(yj, yj, xj * xj));
            }
            __syncthreads();

            const int i = a * TILE + t;
            const float xi = g[3 * i + 0];
            const float yi = g[3 * i + 1];
            const float zi = g[3 * i + 2];
            const float R = fmaf(zi, zi, fmaf(yi, yi, xi * xi));
            const u64 R2 = pack2(R, R);
            const u64 A2 = pack2(-2.0f * xi, -2.0f * xi);
            const u64 B2 = pack2(-2.0f * yi, -2.0f * yi);
            const u64 C2 = pack2(-2.0f * zi, -2.0f * zi);

            const unsigned base = smem_u32(sf);
            const unsigned aX = base, aY = base + TILE * 4,
                           aZ = base + TILE * 8, aR = base + TILE * 12;

            const int m0 = h * (TILE / 4);          /* 64 steps per half */
            const int m1 = m0 + TILE / 4;
            #pragma unroll 4
            for (int m = m0; m < m1; m += 2) {
                const unsigned o8a = (unsigned)m * 8u;
                const unsigned o8b = o8a + 8u;
                u64 sa = addx2(R2, lds64(aR + o8a));
                sa = fmax2(lds64(aX + o8a), A2, sa);
                sa = fmax2(lds64(aY + o8a), B2, sa);
                sa = fmax2(lds64(aZ + o8a), C2, sa);
                u64 sb = addx2(R2, lds64(aR + o8b));
                sb = fmax2(lds64(aX + o8b), A2, sb);
                sb = fmax2(lds64(aY + o8b), B2, sb);
                sb = fmax2(lds64(aZ + o8b), C2, sb);
                float a0, a1, b0, b1;
                unpack2(sa, a0, a1);
                unpack2(sb, b0, b1);
                float mn = fminf(fminf(a0, a1), fminf(b0, b1));
                if (mn < 0.64f) {
                    hit(a0, acc); hit(a1, acc);
                    hit(b0, acc); hit(b1, acc);
                }
            }
        }

        #pragma unroll
        for (int o = 16; o; o >>= 1)
            acc += __shfl_down_sync(0xffffffffu, acc, o);
        if (ln == 0) s_fred[w] = acc;
        __syncthreads();
        if (t == 0) {
            float r = 0.f;
            #pragma unroll
            for (int i2 = 0; i2 < NWARPS; ++i2) r += s_fred[i2];
            g_pair_partial[pid] = (double)r;
        }

    } else if (bid < 2) {
        /* ========= exact quantile pair (ranks k0, k0+1), 3-phase ========= */
        const int qb = bid;
        const unsigned k0 = qb ? 13823u : 4607u;
        const float gA = qb ? 0.6245f : -0.7245f;
        const float gB = qb ? 0.7245f : -0.6245f;
        const float4* gv4 = (const float4*)g;

        float lo = -CUDART_INF_F, hi = CUDART_INF_F;
        unsigned cL = 0, cH = NTOT;
        bool allEq = false;

        for (int it = 0; it < 48; ++it) {
            if (cH - cL <= (unsigned)GMAX) break;
            const unsigned klo = fkey(lo), khi = fkey(hi);
            if (khi - klo <= 1u) { allEq = true; break; }
            float cand;
            if (it == 0)      cand = gA;
            else if (it == 1) cand = gB;
            else if (it < 8) {
                double frac = ((double)k0 + 0.5 - (double)cL) / (double)(cH - cL);
                cand = (float)((double)lo + frac * ((double)hi - (double)lo));
            } else cand = funkey(klo + (khi - klo) / 2u);
            {
                unsigned kc = fkey(cand);
                if (!(kc > klo && kc < khi)) cand = funkey(klo + (khi - klo) / 2u);
            }
            unsigned c = 0;
            #pragma unroll 3
            for (int e = 0; e < V4PT; ++e) {
                float4 q = gv4[t + e * TPB];
                c += (q.x < cand) ? 1u : 0u;
                c += (q.y < cand) ? 1u : 0u;
                c += (q.z < cand) ? 1u : 0u;
                c += (q.w < cand) ? 1u : 0u;
            }
            #pragma unroll
            for (int o = 16; o; o >>= 1) c += __shfl_down_sync(0xffffffffu, c, o);
            if (ln == 0) s_wcnt[w] = c;
            __syncthreads();
            if (t == 0) {
                unsigned totc = 0;
                #pragma unroll
                for (int i2 = 0; i2 < NWARPS; ++i2) totc += s_wcnt[i2];
                s_tot = totc;
            }
            __syncthreads();
            const unsigned ctot = s_tot;
            if (ctot <= k0) { lo = cand; cL = ctot; }
            else            { hi = cand; cH = ctot; }
        }

        if (allEq) {
            if (t == 0) { s_q[0] = lo; s_q[1] = lo; }
            __syncthreads();
        } else {
            float* sub = (float*)smem_raw;
            if (t == 0) s_gcnt = 0;
            __syncthreads();
            #pragma unroll 3
            for (int e = 0; e < V4PT; ++e) {
                float4 q = gv4[t + e * TPB];
                float qq[4] = {q.x, q.y, q.z, q.w};
                #pragma unroll
                for (int c4 = 0; c4 < 4; ++c4) {
                    float x = qq[c4];
                    if (x >= lo && x < hi) {
                        unsigned p = atomicAdd(&s_gcnt, 1u);
                        if (p < (unsigned)GMAX) sub[p] = x;
                    }
                }
            }
            __syncthreads();
            const unsigned mm0 = s_gcnt;
            const unsigned cL0 = cL;

            unsigned cLg = cL, cHg = cH;
            float lo2 = lo, hi2 = hi;
            for (int it = 0; it < 64; ++it) {
                if (cHg - cLg <= (unsigned)SELMAX) break;
                const unsigned klo = fkey(lo2), khi = fkey(hi2);
                if (khi - klo <= 1u) break;
                float cand;
                if (it < 10) {
                    double frac = ((double)k0 + 0.5 - (double)cLg) / (double)(cHg - cLg);
                    cand = (float)((double)lo2 + frac * ((double)hi2 - (double)lo2));
                } else cand = funkey(klo + (khi - klo) / 2u);
                {
                    unsigned kc = fkey(cand);
                    if (!(kc > klo && kc < khi)) cand = funkey(klo + (khi - klo) / 2u);
                }
                unsigned c = 0;
                for (unsigned i2 = t; i2 < mm0; i2 += TPB)
                    c += (sub[i2] < cand) ? 1u : 0u;
                #pragma unroll
                for (int o = 16; o; o >>= 1) c += __shfl_down_sync(0xffffffffu, c, o);
                if (ln == 0) s_wcnt[w] = c;
                __syncthreads();
                if (t == 0) {
                    unsigned totc = 0;
                    #pragma unroll
                    for (int i2 = 0; i2 < NWARPS; ++i2) totc += s_wcnt[i2];
                    s_tot = totc;
                }
                __syncthreads();
                const unsigned cg = cL0 + s_tot;
                if (cg <= k0) { lo2 = cand; cLg = cg; }
                else          { hi2 = cand; cHg = cg; }
            }

            for (unsigned i2 = t; i2 < mm0; i2 += TPB) {
                float x = sub[i2];
                if (x >= lo2 && x < hi2) {
                    unsigned cl = 0, ce = 0;
                    for (unsigned jj = 0; jj < mm0; ++jj) {
                        float y = sub[jj];
                        cl += (y < x) ? 1u : 0u;
                        ce += (y == x) ? 1u : 0u;
                    }
                    const unsigned glo = cL0 + cl;
                    if (glo <= k0 && k0 < glo + ce)           s_q[0] = x;
                    if (glo <= k0 + 1u && k0 + 1u < glo + ce) s_q[1] = x;
                }
            }
            if (k0 + 1u >= cHg) {
                float mn = CUDART_INF_F;
                #pragma unroll 3
                for (int e = 0; e < V4PT; ++e) {
                    float4 q = gv4[t + e * TPB];
                    if (q.x >= hi2) mn = fminf(mn, q.x);
                    if (q.y >= hi2) mn = fminf(mn, q.y);
                    if (q.z >= hi2) mn = fminf(mn, q.z);
                    if (q.w >= hi2) mn = fminf(mn, q.w);
                }
                #pragma unroll
                for (int o = 16; o; o >>= 1)
                    mn = fminf(mn, __shfl_down_sync(0xffffffffu, mn, o));
                if (ln == 0) s_fred[w] = mn;
                __syncthreads();
                if (t == 0) {
                    float r = s_fred[0];
                    #pragma unroll
                    for (int i2 = 1; i2 < NWARPS; ++i2) r = fminf(r, s_fred[i2]);
                    s_q[1] = r;
                }
            }
            __syncthreads();
        }
        if (t == 0) {
            g_qv[2 * qb + 0] = s_q[0];
            g_qv[2 * qb + 1] = s_q[1];
        }

    } else {
        /* ============ std sums (fp64, deterministic) ============ */
        __shared__ double sds[NWARPS], sdq[NWARPS];
        const float4* gv4 = (const float4*)g;
        double s = 0.0, s2 = 0.0;
        #pragma unroll 3
        for (int e = 0; e < V4PT; ++e) {
            float4 q = gv4[t + e * TPB];
            double x0 = (double)q.x, x1 = (double)q.y;
            double x2 = (double)q.z, x3 = (double)q.w;
            s  += (x0 + x1) + (x2 + x3);
            s2 += (x0 * x0 + x1 * x1) + (x2 * x2 + x3 * x3);
        }
        #pragma unroll
        for (int o = 16; o; o >>= 1) {
            s  += __shfl_down_sync(0xffffffffu, s,  o);
            s2 += __shfl_down_sync(0xffffffffu, s2, o);
        }
        if (ln == 0) { sds[w] = s; sdq[w] = s2; }
        __syncthreads();
        if (t == 0) {
            double aa = 0.0, bb = 0.0;
            #pragma unroll
            for (int i2 = 0; i2 < NWARPS; ++i2) { aa += sds[i2]; bb += sdq[i2]; }
            g_sum_d = aa; g_sumsq_d = bb;
        }
    }

    /* ====== two-level completion barrier; last block combines ====== */
    __syncthreads();
    if (t == 0) {
        __threadfence();
        const int r = bid & 31;
        const unsigned quota = (unsigned)(GRID / 32) + ((r < (GRID & 31)) ? 1u : 0u);
        int last = 0;
        unsigned old = atomicAdd(&g_c1[r * 64], 1u);
        if (old == quota - 1u) {
            unsigned old2 = atomicAdd(&g_c2, 1u);
            last = (old2 == 31u);
        }
        s_last = last;
    }
    __syncthreads();
    if (s_last) {
        if (t < 32) {
            __threadfence();
            double s = 0.0;
            for (int i2 = t; i2 < NUNITS; i2 += 32) s += g_pair_partial[i2];
            #pragma unroll
            for (int o = 16; o; o >>= 1) s += __shfl_down_sync(0xffffffffu, s, o);
            g_c1[t * 64] = 0u;
            if (t == 0) {
                g_c2 = 0u;
                double punish = s / NPAIRS_D;
                double var = (g_sumsq_d - g_sum_d * g_sum_d / (double)NTOT)
                             / (double)(NTOT - 1);
                double sd = sqrt(var);
                float q1 = 0.25f * g_qv[0] + 0.75f * g_qv[1];
                float q3 = 0.75f * g_qv[2] + 0.25f * g_qv[3];
                double dstd = sd - RAND_STD;
                double diqr = (double)(q3 - q1) - IQR_RAND;
                out[0] = (float)(punish + dstd * dstd + diqr * diqr);
            }
        }
    }
}

extern "C" void kernel_launch(void* const* d_in, const int* in_sizes, int n_in,
                              void* d_out, int out_size) {
    (void)in_sizes; (void)n_in; (void)out_size;
    const float* g = (const float*)d_in[0];
    float* out = (float*)d_out;
    dp_fused_kernel<<<GRID, TPB, SMEM_BYTES>>>(g, out);
}

// round 10
// speedup vs baseline: 1.3600x; 1.3600x over previous
#include <cuda_runtime.h>
#include <math_constants.h>
#include <stdint.h>

#define NTOT     18432
#define TPB      512
#define TILE     512
#define NSTRIP   12
#define NDIAG    12
#define NUNITS   144                 /* 12 diag + 66*2 offdiag halves */
#define GRID     147
#define NWARPS   16
#define V4PT     9                   /* NTOT/4/TPB */
#define GMAX     1024
#define SELMAX   48
#define SMEM_BYTES 8192              /* float4 tile 512*16 | gather 1024 f32 */

static const double NPAIRS_D = 18871296.0;
static const double RAND_STD = 1.75;
static const double IQR_RAND = 2.45;

__device__ double   g_pair_partial[NUNITS];
__device__ double   g_sum_d, g_sumsq_d;
__device__ float    g_qv[4];
__device__ unsigned g_done = 0;

__device__ __forceinline__ float sqrt_approx(float x) {
    float r; asm("sqrt.approx.f32 %0, %1;" : "=f"(r) : "f"(x)); return r;
}
__device__ __forceinline__ unsigned fkey(float f) {
    unsigned u = __float_as_uint(f);
    return (u & 0x80000000u) ? ~u : (u | 0x80000000u);
}
__device__ __forceinline__ float funkey(unsigned u) {
    unsigned bits = (u & 0x80000000u) ? (u & 0x7fffffffu) : ~u;
    return __uint_as_float(bits);
}
/* rare-hit handler: pen += relu(0.8 - sqrt(sq)) */
__device__ __forceinline__ void hit(float s, float& acc) {
    if (s < 0.64f) acc += 0.8f - sqrt_approx(fmaxf(s, 0.0f));
}
/* squared distance via norm trick from broadcast float4 */
__device__ __forceinline__ float sqd(float4 o, float R, float A, float B, float C) {
    return fmaf(C, o.z, fmaf(B, o.y, fmaf(A, o.x, R + o.w)));
}

__global__ void __launch_bounds__(TPB)
dp_fused_kernel(const float* __restrict__ g, float* __restrict__ out) {
    extern __shared__ unsigned char smem_raw[];
    const int bid = blockIdx.x;
    const int t   = threadIdx.x;
    const int w   = t >> 5;
    const int ln  = t & 31;

    __shared__ unsigned s_wcnt[NWARPS];
    __shared__ unsigned s_tot, s_gcnt;
    __shared__ float    s_fred[NWARPS];
    __shared__ float    s_q[2];
    __shared__ int      s_last;

    if (bid >= 3) {
        /* ===== pairwise: float4 broadcast tile + rare-hit 4-pair screen ===== */
        const int pid = bid - 3;
        int a, b, h;
        if (pid < NDIAG) { a = b = pid; h = -1; }
        else {
            int o = pid - NDIAG;
            int tt = o >> 1; h = o & 1;
            a = 0; int rem = tt;
            while (rem >= NSTRIP - 1 - a) { rem -= NSTRIP - 1 - a; ++a; }
            b = a + 1 + rem;
        }

        float4* tj = (float4*)smem_raw;
        {
            const int j = b * TILE + t;
            float xj = g[3 * j + 0], yj = g[3 * j + 1], zj = g[3 * j + 2];
            tj[t] = make_float4(xj, yj, zj,
                                fmaf(zj, zj, fmaf(yj, yj, xj * xj)));
        }
        /* load i coords before the barrier to overlap */
        float xi, yi, zi;
        {
            const int i = a * TILE + t;
            xi = g[3 * i + 0]; yi = g[3 * i + 1]; zi = g[3 * i + 2];
        }
        __syncthreads();

        const float R = fmaf(zi, zi, fmaf(yi, yi, xi * xi));
        const float A = -2.0f * xi, B = -2.0f * yi, C = -2.0f * zi;

        float acc = 0.f;

        if (h < 0) {
            /* diag: wrap d = 1..255 all threads; d = 256 for t < 256.
               groups of 4 d-values screened together */
            #pragma unroll 1
            for (int d = 1; d <= 252; d += 4) {
                float s0 = sqd(tj[(t + d)     & (TILE - 1)], R, A, B, C);
                float s1 = sqd(tj[(t + d + 1) & (TILE - 1)], R, A, B, C);
                float s2 = sqd(tj[(t + d + 2) & (TILE - 1)], R, A, B, C);
                float s3 = sqd(tj[(t + d + 3) & (TILE - 1)], R, A, B, C);
                float mn = fminf(fminf(s0, s1), fminf(s2, s3));
                if (mn < 0.64f) {
                    hit(s0, acc); hit(s1, acc); hit(s2, acc); hit(s3, acc);
                }
            }
            {   /* d = 253, 254, 255 */
                float s0 = sqd(tj[(t + 253) & (TILE - 1)], R, A, B, C);
                float s1 = sqd(tj[(t + 254) & (TILE - 1)], R, A, B, C);
                float s2 = sqd(tj[(t + 255) & (TILE - 1)], R, A, B, C);
                float mn = fminf(fminf(s0, s1), s2);
                if (mn < 0.64f) { hit(s0, acc); hit(s1, acc); hit(s2, acc); }
            }
            if (t < TILE / 2) {
                float s0 = sqd(tj[(t + 256) & (TILE - 1)], R, A, B, C);
                hit(s0, acc);
            }
        } else {
            const int j0 = h * (TILE / 2);
            const int j1 = j0 + TILE / 2;
            #pragma unroll 2
            for (int jj = j0; jj < j1; jj += 4) {
                float s0 = sqd(tj[jj + 0], R, A, B, C);
                float s1 = sqd(tj[jj + 1], R, A, B, C);
                float s2 = sqd(tj[jj + 2], R, A, B, C);
                float s3 = sqd(tj[jj + 3], R, A, B, C);
                float mn = fminf(fminf(s0, s1), fminf(s2, s3));
                if (mn < 0.64f) {
                    hit(s0, acc); hit(s1, acc); hit(s2, acc); hit(s3, acc);
                }
            }
        }

        #pragma unroll
        for (int o = 16; o; o >>= 1)
            acc += __shfl_down_sync(0xffffffffu, acc, o);
        if (ln == 0) s_fred[w] = acc;
        __syncthreads();
        if (t == 0) {
            float r = 0.f;
            #pragma unroll
            for (int i2 = 0; i2 < NWARPS; ++i2) r += s_fred[i2];
            g_pair_partial[pid] = (double)r;
        }

    } else if (bid < 2) {
        /* ========= exact quantile pair (ranks k0, k0+1), 3-phase ========= */
        const int qb = bid;
        const unsigned k0 = qb ? 13823u : 4607u;
        const float gA = qb ? 0.6245f : -0.7245f;
        const float gB = qb ? 0.7245f : -0.6245f;
        const float4* gv4 = (const float4*)g;

        float lo = -CUDART_INF_F, hi = CUDART_INF_F;
        unsigned cL = 0, cH = NTOT;
        bool allEq = false;

        /* ---- phase 1: gmem passes (L1/L2-resident) until bracket <= GMAX ---- */
        for (int it = 0; it < 48; ++it) {
            if (cH - cL <= (unsigned)GMAX) break;
            const unsigned klo = fkey(lo), khi = fkey(hi);
            if (khi - klo <= 1u) { allEq = true; break; }
            float cand;
            if (it == 0)      cand = gA;
            else if (it == 1) cand = gB;
            else if (it < 8) {
                double frac = ((double)k0 + 0.5 - (double)cL) / (double)(cH - cL);
                cand = (float)((double)lo + frac * ((double)hi - (double)lo));
            } else cand = funkey(klo + (khi - klo) / 2u);
            {
                unsigned kc = fkey(cand);
                if (!(kc > klo && kc < khi)) cand = funkey(klo + (khi - klo) / 2u);
            }
            unsigned c = 0;
            #pragma unroll
            for (int e = 0; e < V4PT; ++e) {
                float4 q = gv4[t + e * TPB];
                c += (q.x < cand) ? 1u : 0u;
                c += (q.y < cand) ? 1u : 0u;
                c += (q.z < cand) ? 1u : 0u;
                c += (q.w < cand) ? 1u : 0u;
            }
            #pragma unroll
            for (int o = 16; o; o >>= 1) c += __shfl_down_sync(0xffffffffu, c, o);
            if (ln == 0) s_wcnt[w] = c;
            __syncthreads();
            if (t == 0) {
                unsigned totc = 0;
                #pragma unroll
                for (int i2 = 0; i2 < NWARPS; ++i2) totc += s_wcnt[i2];
                s_tot = totc;
            }
            __syncthreads();
            const unsigned ctot = s_tot;
            if (ctot <= k0) { lo = cand; cL = ctot; }
            else            { hi = cand; cH = ctot; }
        }

        if (allEq) {
            if (t == 0) { s_q[0] = lo; s_q[1] = lo; }
            __syncthreads();
        } else {
            /* ---- gather bracket [lo,hi) into smem ---- */
            float* sub = (float*)smem_raw;
            if (t == 0) s_gcnt = 0;
            __syncthreads();
            #pragma unroll
            for (int e = 0; e < V4PT; ++e) {
                float4 q = gv4[t + e * TPB];
                float qq[4] = {q.x, q.y, q.z, q.w};
                #pragma unroll
                for (int c4 = 0; c4 < 4; ++c4) {
                    float x = qq[c4];
                    if (x >= lo && x < hi) {
                        unsigned p = atomicAdd(&s_gcnt, 1u);
                        if (p < (unsigned)GMAX) sub[p] = x;
                    }
                }
            }
            __syncthreads();
            const unsigned mm0 = s_gcnt;
            const unsigned cL0 = cL;

            /* ---- phase 2: smem count passes until bracket <= SELMAX ---- */
            unsigned cLg = cL, cHg = cH;
            float lo2 = lo, hi2 = hi;
            for (int it = 0; it < 64; ++it) {
                if (cHg - cLg <= (unsigned)SELMAX) break;
                const unsigned klo = fkey(lo2), khi = fkey(hi2);
                if (khi - klo <= 1u) break;
                float cand;
                if (it < 10) {
                    double frac = ((double)k0 + 0.5 - (double)cLg) / (double)(cHg - cLg);
                    cand = (float)((double)lo2 + frac * ((double)hi2 - (double)lo2));
                } else cand = funkey(klo + (khi - klo) / 2u);
                {
                    unsigned kc = fkey(cand);
                    if (!(kc > klo && kc < khi)) cand = funkey(klo + (khi - klo) / 2u);
                }
                unsigned c = 0;
                for (unsigned i2 = t; i2 < mm0; i2 += TPB)
                    c += (sub[i2] < cand) ? 1u : 0u;
                #pragma unroll
                for (int o = 16; o; o >>= 1) c += __shfl_down_sync(0xffffffffu, c, o);
                if (ln == 0) s_wcnt[w] = c;
                __syncthreads();
                if (t == 0) {
                    unsigned totc = 0;
                    #pragma unroll
                    for (int i2 = 0; i2 < NWARPS; ++i2) totc += s_wcnt[i2];
                    s_tot = totc;
                }
                __syncthreads();
                const unsigned cg = cL0 + s_tot;
                if (cg <= k0) { lo2 = cand; cLg = cg; }
                else          { hi2 = cand; cHg = cg; }
            }

            /* ---- phase 3: exact select on tiny bracket ---- */
            for (unsigned i2 = t; i2 < mm0; i2 += TPB) {
                float x = sub[i2];
                if (x >= lo2 && x < hi2) {
                    unsigned cl = 0, ce = 0;
                    for (unsigned jj = 0; jj < mm0; ++jj) {
                        float y = sub[jj];
                        cl += (y < x) ? 1u : 0u;
                        ce += (y == x) ? 1u : 0u;
                    }
                    const unsigned glo = cL0 + cl;
                    if (glo <= k0 && k0 < glo + ce)           s_q[0] = x;
                    if (glo <= k0 + 1u && k0 + 1u < glo + ce) s_q[1] = x;
                }
            }
            /* successor outside bracket: min element >= hi2 */
            if (k0 + 1u >= cHg) {
                float mn = CUDART_INF_F;
                #pragma unroll
                for (int e = 0; e < V4PT; ++e) {
                    float4 q = gv4[t + e * TPB];
                    if (q.x >= hi2) mn = fminf(mn, q.x);
                    if (q.y >= hi2) mn = fminf(mn, q.y);
                    if (q.z >= hi2) mn = fminf(mn, q.z);
                    if (q.w >= hi2) mn = fminf(mn, q.w);
                }
                #pragma unroll
                for (int o = 16; o; o >>= 1)
                    mn = fminf(mn, __shfl_down_sync(0xffffffffu, mn, o));
                if (ln == 0) s_fred[w] = mn;
                __syncthreads();
                if (t == 0) {
                    float r = s_fred[0];
                    #pragma unroll
                    for (int i2 = 1; i2 < NWARPS; ++i2) r = fminf(r, s_fred[i2]);
                    s_q[1] = r;
                }
            }
            __syncthreads();
        }
        if (t == 0) {
            g_qv[2 * qb + 0] = s_q[0];
            g_qv[2 * qb + 1] = s_q[1];
        }

    } else {
        /* ============ std sums (fp64, deterministic) ============ */
        __shared__ double sds[NWARPS], sdq[NWARPS];
        const float4* gv4 = (const float4*)g;
        double s = 0.0, s2 = 0.0;
        #pragma unroll
        for (int e = 0; e < V4PT; ++e) {
            float4 q = gv4[t + e * TPB];
            double x0 = (double)q.x, x1 = (double)q.y;
            double x2 = (double)q.z, x3 = (double)q.w;
            s  += (x0 + x1) + (x2 + x3);
            s2 += (x0 * x0 + x1 * x1) + (x2 * x2 + x3 * x3);
        }
        #pragma unroll
        for (int o = 16; o; o >>= 1) {
            s  += __shfl_down_sync(0xffffffffu, s,  o);
            s2 += __shfl_down_sync(0xffffffffu, s2, o);
        }
        if (ln == 0) { sds[w] = s; sdq[w] = s2; }
        __syncthreads();
        if (t == 0) {
            double aa = 0.0, bb = 0.0;
            #pragma unroll
            for (int i2 = 0; i2 < NWARPS; ++i2) { aa += sds[i2]; bb += sdq[i2]; }
            g_sum_d = aa; g_sumsq_d = bb;
        }
    }

    /* ====== epilogue: thread-0 release; last block combines ====== */
    __syncthreads();
    if (t == 0) {
        __threadfence();
        unsigned old = atomicAdd(&g_done, 1u);
        s_last = (old == (unsigned)(GRID - 1)) ? 1 : 0;
    }
    __syncthreads();
    if (s_last) {
        if (t < 32) {
            __threadfence();
            double s = 0.0;
            for (int i2 = t; i2 < NUNITS; i2 += 32) s += g_pair_partial[i2];
            #pragma unroll
            for (int o = 16; o; o >>= 1) s += __shfl_down_sync(0xffffffffu, s, o);
            if (t == 0) {
                double punish = s / NPAIRS_D;
                double var = (g_sumsq_d - g_sum_d * g_sum_d / (double)NTOT)
                             / (double)(NTOT - 1);
                double sd = sqrt(var);
                float q1 = 0.25f * g_qv[0] + 0.75f * g_qv[1];
                float q3 = 0.75f * g_qv[2] + 0.25f * g_qv[3];
                double dstd = sd - RAND_STD;
                double diqr = (double)(q3 - q1) - IQR_RAND;
                out[0] = (float)(punish + dstd * dstd + diqr * diqr);
                g_done = 0;   /* reset for next graph replay */
            }
        }
    }
}

extern "C" void kernel_launch(void* const* d_in, const int* in_sizes, int n_in,
                              void* d_out, int out_size) {
    (void)in_sizes; (void)n_in; (void)out_size;
    const float* g = (const float*)d_in[0];
    float* out = (float*)d_out;
    dp_fused_kernel<<<GRID, TPB, SMEM_BYTES>>>(g, out);
}